// round 10
// baseline (speedup 1.0000x reference)
#include <cuda_runtime.h>
#include <cuda_bf16.h>
#include <math.h>
#include <stdint.h>

// ---------------------------------------------------------------------------
#define BB 16
#define MM 2048
#define FD 128
#define TSQ 128
#define NT (MM / TSQ)                 // 16
#define NPAIR (NT * (NT + 1) / 2)     // 136
#define PITCHB 272                    // bf16 plane row pitch bytes (256 + 16 pad)
#define PLANE_B (TSQ * PITCHB)        // 34816
#define SMEM_BYTES (4 * PLANE_B)      // 139264

// Scratch
__device__ __align__(128) float          g_xnorm[BB * MM * FD];     // 16 MB
__device__ __align__(128) __nv_bfloat16  g_xhi[BB * MM * FD];       // 8.4 MB
__device__ __align__(128) __nv_bfloat16  g_xlo[BB * MM * FD];       // 8.4 MB
// per (row, tile) top-4 approx candidates: 2 float4 {v1,i1,v2,i2},{v3,i3,v4,i4}
__device__ __align__(128) float4         g_cand[(size_t)BB * MM * NT * 2];

// ---------------------------------------------------------------------------
__device__ __forceinline__ uint32_t smem_u32(const void* p) {
    uint32_t a;
    asm("{ .reg .u64 t; cvta.to.shared.u64 t, %1; cvt.u32.u64 %0, t; }"
        : "=r"(a) : "l"(p));
    return a;
}

__device__ __forceinline__ void ldmx4(uint32_t* r, uint32_t addr) {
    asm volatile("ldmatrix.sync.aligned.m8n8.x4.shared.b16 {%0,%1,%2,%3}, [%4];"
        : "=r"(r[0]), "=r"(r[1]), "=r"(r[2]), "=r"(r[3]) : "r"(addr));
}

__device__ __forceinline__ void mma_bf16(float* c, const uint32_t* a, const uint32_t* b) {
    asm volatile(
        "mma.sync.aligned.m16n8k16.row.col.f32.bf16.bf16.f32 "
        "{%0,%1,%2,%3}, {%4,%5,%6,%7}, {%8,%9}, {%0,%1,%2,%3};"
        : "+f"(c[0]), "+f"(c[1]), "+f"(c[2]), "+f"(c[3])
        : "r"(a[0]), "r"(a[1]), "r"(a[2]), "r"(a[3]), "r"(b[0]), "r"(b[1]));
}

__device__ __forceinline__ bool better(float v, int k, float V, int I) {
    return (v > V) || (v == V && k < I);
}

__device__ __forceinline__ void top4_update(float v, int k, float* V, int* I) {
    if (!better(v, k, V[3], I[3])) return;
    if (better(v, k, V[2], I[2])) {
        V[3] = V[2]; I[3] = I[2];
        if (better(v, k, V[1], I[1])) {
            V[2] = V[1]; I[2] = I[1];
            if (better(v, k, V[0], I[0])) {
                V[1] = V[0]; I[1] = I[0]; V[0] = v; I[0] = k;
            } else { V[1] = v; I[1] = k; }
        } else { V[2] = v; I[2] = k; }
    } else { V[3] = v; I[3] = k; }
}

// ---------------------------------------------------------------------------
// Kernel 1: normalize + bf16 hi/lo split. One warp per row.
// ---------------------------------------------------------------------------
__global__ void prep_kernel(const float* __restrict__ x) {
    int row  = blockIdx.x * 8 + (threadIdx.x >> 5);
    int lane = threadIdx.x & 31;
    float4 v = reinterpret_cast<const float4*>(x + (size_t)row * FD)[lane];
    float ss = v.x * v.x + v.y * v.y + v.z * v.z + v.w * v.w;
    #pragma unroll
    for (int o = 16; o > 0; o >>= 1) ss += __shfl_xor_sync(0xffffffffu, ss, o);
    float inv = 1.0f / fmaxf(sqrtf(ss), 1e-12f);
    v.x *= inv; v.y *= inv; v.z *= inv; v.w *= inv;
    reinterpret_cast<float4*>(g_xnorm + (size_t)row * FD)[lane] = v;

    __nv_bfloat16 h0 = __float2bfloat16(v.x), h1 = __float2bfloat16(v.y);
    __nv_bfloat16 h2 = __float2bfloat16(v.z), h3 = __float2bfloat16(v.w);
    __nv_bfloat16 l0 = __float2bfloat16(v.x - __bfloat162float(h0));
    __nv_bfloat16 l1 = __float2bfloat16(v.y - __bfloat162float(h1));
    __nv_bfloat16 l2 = __float2bfloat16(v.z - __bfloat162float(h2));
    __nv_bfloat16 l3 = __float2bfloat16(v.w - __bfloat162float(h3));
    uint2 hp, lp;
    hp.x = (uint32_t)__bfloat16_as_ushort(h0) | ((uint32_t)__bfloat16_as_ushort(h1) << 16);
    hp.y = (uint32_t)__bfloat16_as_ushort(h2) | ((uint32_t)__bfloat16_as_ushort(h3) << 16);
    lp.x = (uint32_t)__bfloat16_as_ushort(l0) | ((uint32_t)__bfloat16_as_ushort(l1) << 16);
    lp.y = (uint32_t)__bfloat16_as_ushort(l2) | ((uint32_t)__bfloat16_as_ushort(l3) << 16);
    reinterpret_cast<uint2*>(g_xhi + (size_t)row * FD)[lane] = hp;
    reinterpret_cast<uint2*>(g_xlo + (size_t)row * FD)[lane] = lp;
}

// ---------------------------------------------------------------------------
// Kernel 2: symmetric tile-pair GEMM via mma.sync bf16 (3-term compensation).
// Grid (NPAIR, BB), block 256 = 8 warps (2 q-warps x 4 k-warps).
// Emits per-(row, tile) approx top-4 candidates, both orientations.
// ---------------------------------------------------------------------------
__global__ void __launch_bounds__(256, 1) pair_kernel() {
    extern __shared__ char smem[];
    const uint32_t sb = smem_u32(smem);
    const int tid  = threadIdx.x;
    const int lane = tid & 31;
    const int wid  = tid >> 5;
    const int qw   = wid >> 2;          // 0-1
    const int kw   = wid & 3;           // 0-3
    const int b    = blockIdx.y;

    int t = blockIdx.x, ti = 0, n = NT;
    while (t >= n) { t -= n; n--; ti++; }
    const int tj    = ti + t;
    const int ibase = ti * TSQ;
    const int jbase = tj * TSQ;

    // ---- load bf16 planes into padded smem (full 256B rows: 32 uint2/row) ----
    const uint32_t QHI = 0, QLO = PLANE_B, KHI = 2 * PLANE_B, KLO = 3 * PLANE_B;
    {
        const uint2* sq_h = reinterpret_cast<const uint2*>(g_xhi + (size_t)(b * MM + ibase) * FD);
        const uint2* sq_l = reinterpret_cast<const uint2*>(g_xlo + (size_t)(b * MM + ibase) * FD);
        #pragma unroll
        for (int p = 0; p < 16; p++) {
            int idx = tid + p * 256;          // 0..4095
            int r = idx >> 5, c = idx & 31;   // 32 x 8B per row
            *reinterpret_cast<uint2*>(smem + QHI + r * PITCHB + c * 8) = sq_h[r * 32 + c];
            *reinterpret_cast<uint2*>(smem + QLO + r * PITCHB + c * 8) = sq_l[r * 32 + c];
        }
    }
    uint32_t KHIo = KHI, KLOo = KLO;
    if (ti == tj) { KHIo = QHI; KLOo = QLO; }
    else {
        const uint2* sk_h = reinterpret_cast<const uint2*>(g_xhi + (size_t)(b * MM + jbase) * FD);
        const uint2* sk_l = reinterpret_cast<const uint2*>(g_xlo + (size_t)(b * MM + jbase) * FD);
        #pragma unroll
        for (int p = 0; p < 16; p++) {
            int idx = tid + p * 256;
            int r = idx >> 5, c = idx & 31;
            *reinterpret_cast<uint2*>(smem + KHI + r * PITCHB + c * 8) = sk_h[r * 32 + c];
            *reinterpret_cast<uint2*>(smem + KLO + r * PITCHB + c * 8) = sk_l[r * 32 + c];
        }
    }
    __syncthreads();

    // ---- fragment addressing ----
    uint32_t aoff[4], boff[2];
    #pragma unroll
    for (int mt = 0; mt < 4; mt++)
        aoff[mt] = (uint32_t)(qw * 64 + mt * 16 + (lane & 15)) * PITCHB + ((lane >> 4) << 4);
    {
        int sel = lane >> 3, j = lane & 7;
        #pragma unroll
        for (int p = 0; p < 2; p++)
            boff[p] = (uint32_t)(kw * 32 + p * 16 + ((sel >> 1) << 3) + j) * PITCHB
                      + ((sel & 1) << 4);
    }

    float c[4][4][4];
    #pragma unroll
    for (int mt = 0; mt < 4; mt++)
        #pragma unroll
        for (int nt = 0; nt < 4; nt++)
            #pragma unroll
            for (int e = 0; e < 4; e++) c[mt][nt][e] = 0.0f;

    // ---- mma main loop: f in steps of 16 ----
    #pragma unroll
    for (int fs = 0; fs < 8; fs++) {
        const uint32_t fb = fs * 32;   // 16 bf16 * 2B
        uint32_t ah[4][4], al[4][4], bh[2][4], bl[2][4];
        #pragma unroll
        for (int mt = 0; mt < 4; mt++) {
            ldmx4(ah[mt], sb + QHI + aoff[mt] + fb);
            ldmx4(al[mt], sb + QLO + aoff[mt] + fb);
        }
        #pragma unroll
        for (int p = 0; p < 2; p++) {
            ldmx4(bh[p], sb + KHIo + boff[p] + fb);
            ldmx4(bl[p], sb + KLOo + boff[p] + fb);
        }
        #pragma unroll
        for (int mt = 0; mt < 4; mt++) {
            #pragma unroll
            for (int nt = 0; nt < 4; nt++) {
                const uint32_t* B1 = &bh[nt >> 1][(nt & 1) * 2];
                const uint32_t* B2 = &bl[nt >> 1][(nt & 1) * 2];
                mma_bf16(c[mt][nt], ah[mt], B1);   // hi*hi
                mma_bf16(c[mt][nt], ah[mt], B2);   // hi*lo
                mma_bf16(c[mt][nt], al[mt], B1);   // lo*hi
            }
        }
    }

    // ---- zero diagonal (diagonal pairs only) ----
    if (ti == tj) {
        #pragma unroll
        for (int mt = 0; mt < 4; mt++)
            #pragma unroll
            for (int nt = 0; nt < 4; nt++)
                #pragma unroll
                for (int e = 0; e < 4; e++) {
                    int r = qw * 64 + mt * 16 + (lane >> 2) + ((e >> 1) << 3);
                    int cc = kw * 32 + nt * 8 + (lane & 3) * 2 + (e & 1);
                    if (r == cc) c[mt][nt][e] = 0.0f;
                }
    }

    float* cv = reinterpret_cast<float*>(smem);             // [128][64]
    int*   ci = reinterpret_cast<int*>(smem + 32768);       // [128][64]

    // ---- Pass 1: row-wise per-thread top-4 -> smem -> per-row top-4 ----
    __syncthreads();
    {
        const int cid = kw * 4 + (lane & 3);
        #pragma unroll
        for (int mt = 0; mt < 4; mt++) {
            #pragma unroll
            for (int half = 0; half < 2; half++) {
                float V[4] = {-INFINITY, -INFINITY, -INFINITY, -INFINITY};
                int   I[4] = {0x7fffffff, 0x7fffffff, 0x7fffffff, 0x7fffffff};
                #pragma unroll
                for (int nt = 0; nt < 4; nt++)
                    #pragma unroll
                    for (int par = 0; par < 2; par++)
                        top4_update(c[mt][nt][half * 2 + par],
                                    jbase + kw * 32 + nt * 8 + (lane & 3) * 2 + par, V, I);
                int r = qw * 64 + mt * 16 + (lane >> 2) + half * 8;
                #pragma unroll
                for (int s = 0; s < 4; s++) {
                    cv[r * 64 + cid * 4 + s] = V[s];
                    ci[r * 64 + cid * 4 + s] = I[s];
                }
            }
        }
    }
    __syncthreads();
    if (tid < TSQ) {
        float V[4] = {-INFINITY, -INFINITY, -INFINITY, -INFINITY};
        int   I[4] = {0x7fffffff, 0x7fffffff, 0x7fffffff, 0x7fffffff};
        #pragma unroll 8
        for (int s = 0; s < 64; s++)
            top4_update(cv[tid * 64 + s], ci[tid * 64 + s], V, I);
        size_t base = ((size_t)(b * MM + ibase + tid) * NT + tj) * 2;
        g_cand[base]     = make_float4(V[0], __int_as_float(I[0]), V[1], __int_as_float(I[1]));
        g_cand[base + 1] = make_float4(V[2], __int_as_float(I[2]), V[3], __int_as_float(I[3]));
    }

    // ---- Pass 2: col-wise (ti != tj) ----
    if (ti != tj) {
        __syncthreads();
        const int cid = qw * 8 + (lane >> 2);
        #pragma unroll
        for (int nt = 0; nt < 4; nt++) {
            #pragma unroll
            for (int par = 0; par < 2; par++) {
                float V[4] = {-INFINITY, -INFINITY, -INFINITY, -INFINITY};
                int   I[4] = {0x7fffffff, 0x7fffffff, 0x7fffffff, 0x7fffffff};
                #pragma unroll
                for (int mt = 0; mt < 4; mt++)
                    #pragma unroll
                    for (int half = 0; half < 2; half++)
                        top4_update(c[mt][nt][half * 2 + par],
                                    ibase + qw * 64 + mt * 16 + (lane >> 2) + half * 8, V, I);
                int cl = kw * 32 + nt * 8 + (lane & 3) * 2 + par;
                #pragma unroll
                for (int s = 0; s < 4; s++) {
                    cv[cl * 64 + cid * 4 + s] = V[s];
                    ci[cl * 64 + cid * 4 + s] = I[s];
                }
            }
        }
        __syncthreads();
        if (tid < TSQ) {
            float V[4] = {-INFINITY, -INFINITY, -INFINITY, -INFINITY};
            int   I[4] = {0x7fffffff, 0x7fffffff, 0x7fffffff, 0x7fffffff};
            #pragma unroll 8
            for (int s = 0; s < 64; s++)
                top4_update(cv[tid * 64 + s], ci[tid * 64 + s], V, I);
            size_t base = ((size_t)(b * MM + jbase + tid) * NT + ti) * 2;
            g_cand[base]     = make_float4(V[0], __int_as_float(I[0]), V[1], __int_as_float(I[1]));
            g_cand[base + 1] = make_float4(V[2], __int_as_float(I[2]), V[3], __int_as_float(I[3]));
        }
    }
}

// ---------------------------------------------------------------------------
// Kernel 3: per-row: merge 64 approx cands -> approx top-4 -> exact fp32
// rescore -> exact top-2 -> symmetric scatter. One warp per row.
// ---------------------------------------------------------------------------
__global__ void reduce_kernel(float* __restrict__ out) {
    int row  = blockIdx.x * 8 + (threadIdx.x >> 5);
    int lane = threadIdx.x & 31;
    int b = row >> 11, m = row & (MM - 1);

    // lane holds 2 candidates (even lane: ranks 1,2; odd lane: ranks 3,4)
    float4 f4 = g_cand[(size_t)row * NT * 2 + (lane >> 1) * 2 + (lane & 1)];
    float va = f4.x; int ia = __float_as_int(f4.y);
    float vb = f4.z; int ib = __float_as_int(f4.w);

    // approx top-4 via iterative warp-argmax (indices distinct across lanes)
    int besti[4];
    #pragma unroll
    for (int s = 0; s < 4; s++) {
        float mv = va; int mi = ia;
        #pragma unroll
        for (int o = 16; o > 0; o >>= 1) {
            float ov = __shfl_xor_sync(0xffffffffu, mv, o);
            int   oi = __shfl_xor_sync(0xffffffffu, mi, o);
            if (better(ov, oi, mv, mi)) { mv = ov; mi = oi; }
        }
        besti[s] = mi;
        if (ia == mi) { va = vb; ia = ib; vb = -INFINITY; ib = 0x7fffffff; }
    }

    // exact fp32 rescore of the 4 candidates
    const float* Xb = g_xnorm + (size_t)b * MM * FD;
    float4 a = reinterpret_cast<const float4*>(Xb + (size_t)m * FD)[lane];
    float V1 = -INFINITY, V2 = -INFINITY;
    int   I1 = 0x7fffffff, I2 = 0x7fffffff;
    #pragma unroll
    for (int s = 0; s < 4; s++) {
        int idx = besti[s];
        if ((unsigned)idx >= (unsigned)MM) continue;   // safety: skip sentinels
        float d = 0.0f;
        if (idx != m) {
            float4 bv = reinterpret_cast<const float4*>(Xb + (size_t)idx * FD)[lane];
            d = a.x * bv.x + a.y * bv.y + a.z * bv.z + a.w * bv.w;
            #pragma unroll
            for (int o = 16; o > 0; o >>= 1) d += __shfl_xor_sync(0xffffffffu, d, o);
        }
        if (better(d, idx, V1, I1)) { V2 = V1; I2 = I1; V1 = d; I1 = idx; }
        else if (better(d, idx, V2, I2)) { V2 = d; I2 = idx; }
    }

    if (lane == 0 && I1 < MM && I2 < MM) {
        float* O = out + (size_t)b * MM * MM;
        atomicAdd(O + (size_t)m * MM + I1, 0.5f * V1);
        atomicAdd(O + (size_t)I1 * MM + m, 0.5f * V1);
        atomicAdd(O + (size_t)m * MM + I2, 0.5f * V2);
        atomicAdd(O + (size_t)I2 * MM + m, 0.5f * V2);
    }
}

// ---------------------------------------------------------------------------
extern "C" void kernel_launch(void* const* d_in, const int* in_sizes, int n_in,
                              void* d_out, int out_size) {
    const float* x = (const float*)d_in[0];
    float* out = (float*)d_out;

    cudaMemsetAsync(out, 0, (size_t)out_size * sizeof(float));

    prep_kernel<<<(BB * MM) / 8, 256>>>(x);

    cudaFuncSetAttribute(pair_kernel,
                         cudaFuncAttributeMaxDynamicSharedMemorySize, SMEM_BYTES);
    dim3 grid(NPAIR, BB);
    pair_kernel<<<grid, 256, SMEM_BYTES>>>();

    reduce_kernel<<<(BB * MM) / 8, 256>>>(out);
}

// round 11
// speedup vs baseline: 1.8235x; 1.8235x over previous
#include <cuda_runtime.h>
#include <math.h>
#include <stdint.h>

// ---------------------------------------------------------------------------
// Problem constants
// ---------------------------------------------------------------------------
#define BB 16
#define MM 2048
#define FD 128
#define TSQ 128                      // q rows per CTA
#define TSK 64                       // k cols per CTA (half tile)
#define NT (MM / TSQ)                // 16 tiles
#define NPAIR (NT * (NT + 1) / 2)    // 136 tile pairs (ti <= tj)
#define SSTRIDE 132                  // floats per smem row (128 + 4 pad)
#define SMEM_BYTES ((TSQ + TSK) * SSTRIDE * 4)   // 101376 B -> 2 CTAs/SM
// zero-fill slice per CTA (floats, multiple of 4): 272 CTAs per batch plane
#define ZCHUNK 15424                 // 272 * 15424 = 4195328 >= 2048*2048

// Scratch (device globals; no allocation allowed)
__device__ __align__(128) float  g_xnorm[BB * MM * FD];       // 16 MB
// Candidates: [b*M + row][slot(32)][2] float2 {val, idx-bits}
__device__ __align__(128) float2 g_cand[(size_t)BB * MM * 32 * 2];   // 16.8 MB

// ---------------------------------------------------------------------------
__device__ __forceinline__ unsigned long long fma2(unsigned long long a,
                                                   unsigned long long b,
                                                   unsigned long long c) {
    unsigned long long d;
    asm("fma.rn.f32x2 %0, %1, %2, %3;" : "=l"(d) : "l"(a), "l"(b), "l"(c));
    return d;
}

__device__ __forceinline__ float fold2(unsigned long long v) {
    float lo = __uint_as_float((unsigned)(v & 0xffffffffull));
    float hi = __uint_as_float((unsigned)(v >> 32));
    return lo + hi;
}

// top-2 update, jax tie-break (equal value -> lower index); candidates distinct
__device__ __forceinline__ void top2_update(float v, int k,
                                            float& v1, int& i1, float& v2, int& i2) {
    bool b1 = (v > v1) || (v == v1 && k < i1);
    bool b2 = (v > v2) || (v == v2 && k < i2);
    if (b1)      { v2 = v1; i2 = i1; v1 = v; i1 = k; }
    else if (b2) { v2 = v;  i2 = k; }
}

// butterfly-merge variant: partners carry identical winners -> dedup by index
__device__ __forceinline__ void top2_merge(float v, int k,
                                           float& v1, int& i1, float& v2, int& i2) {
    if (k == i1 || k == i2) return;
    top2_update(v, k, v1, i1, v2, i2);
}

// ---------------------------------------------------------------------------
// Kernel 1: L2-normalize each row (one warp per row)
// ---------------------------------------------------------------------------
__global__ void normalize_kernel(const float* __restrict__ x) {
    int row  = blockIdx.x * 8 + (threadIdx.x >> 5);
    int lane = threadIdx.x & 31;
    float4 v = reinterpret_cast<const float4*>(x + (size_t)row * FD)[lane];
    float ss = v.x * v.x + v.y * v.y + v.z * v.z + v.w * v.w;
    #pragma unroll
    for (int o = 16; o > 0; o >>= 1) ss += __shfl_xor_sync(0xffffffffu, ss, o);
    float inv = 1.0f / fmaxf(sqrtf(ss), 1e-12f);
    v.x *= inv; v.y *= inv; v.z *= inv; v.w *= inv;
    reinterpret_cast<float4*>(g_xnorm + (size_t)row * FD)[lane] = v;
}

// ---------------------------------------------------------------------------
// Kernel 2: symmetric tile-pair GEMM, 128(q) x 64(k) per CTA, 8x4 micro-tile.
// Grid: (NPAIR, 2, BB). Block 256 = 16(tx, k) x 16(ty, q). 2 CTAs/SM.
// Also zero-fills a disjoint slice of the output (replaces the memset node;
// the stores drain behind the FMA mainloop).
// ---------------------------------------------------------------------------
__global__ void __launch_bounds__(256, 2) pair_kernel(float* __restrict__ out) {
    extern __shared__ float smem[];
    float* Qs = smem;                      // TSQ x SSTRIDE
    float* Ks = smem + TSQ * SSTRIDE;      // TSK x SSTRIDE

    const int tid   = threadIdx.x;
    const int tx    = tid & 15;
    const int ty    = tid >> 4;
    const int chunk = blockIdx.y;          // which 64-col half of the k tile
    const int b     = blockIdx.z;

    // ---- zero-fill my slice of out[b] (coalesced float4 stores) ----
    {
        const int cta = blockIdx.x * 2 + chunk;          // 0..271
        float* O = out + (size_t)b * MM * MM;
        size_t beg = (size_t)cta * ZCHUNK;
        size_t end = beg + ZCHUNK;
        if (end > (size_t)MM * MM) end = (size_t)MM * MM;
        const float4 z = make_float4(0.f, 0.f, 0.f, 0.f);
        #pragma unroll 4
        for (size_t i = beg + (size_t)tid * 4; i < end; i += 256 * 4)
            *reinterpret_cast<float4*>(O + i) = z;
    }

    // decode tile pair (ti <= tj)
    int t = blockIdx.x, ti = 0, n = NT;
    while (t >= n) { t -= n; n--; ti++; }
    const int tj    = ti + t;
    const int ibase = ti * TSQ;
    const int kbase = tj * TSQ + chunk * TSK;

    const float* Xb = g_xnorm + (size_t)b * MM * FD;

    // Load Q tile: 128 rows x 32 float4, coalesced (16 per thread)
    #pragma unroll
    for (int p = 0; p < 16; p++) {
        int idx = tid + p * 256;
        int r = idx >> 5, c4 = idx & 31;
        float4 v = reinterpret_cast<const float4*>(Xb + (size_t)(ibase + r) * FD)[c4];
        *reinterpret_cast<float4*>(Qs + r * SSTRIDE + c4 * 4) = v;
    }
    // Load K tile: 64 rows x 32 float4 (8 per thread)
    #pragma unroll
    for (int p = 0; p < 8; p++) {
        int idx = tid + p * 256;
        int r = idx >> 5, c4 = idx & 31;
        float4 v = reinterpret_cast<const float4*>(Xb + (size_t)(kbase + r) * FD)[c4];
        *reinterpret_cast<float4*>(Ks + r * SSTRIDE + c4 * 4) = v;
    }
    __syncthreads();

    // 8x4 micro-tile, packed-f32x2 accumulation (pairs along f).
    unsigned long long acc2[8][4];
    #pragma unroll
    for (int i = 0; i < 8; i++)
        #pragma unroll
        for (int j = 0; j < 4; j++) acc2[i][j] = 0ull;

    #pragma unroll 2
    for (int f = 0; f < FD; f += 4) {
        ulonglong2 k2[4];
        #pragma unroll
        for (int j = 0; j < 4; j++)
            k2[j] = *reinterpret_cast<const ulonglong2*>(Ks + (tx + 16 * j) * SSTRIDE + f);
        #pragma unroll
        for (int half = 0; half < 2; half++) {
            ulonglong2 q2[4];
            #pragma unroll
            for (int i = 0; i < 4; i++)
                q2[i] = *reinterpret_cast<const ulonglong2*>(
                    Qs + (ty + 16 * (half * 4 + i)) * SSTRIDE + f);
            #pragma unroll
            for (int i = 0; i < 4; i++) {
                #pragma unroll
                for (int j = 0; j < 4; j++) {
                    acc2[half * 4 + i][j] = fma2(q2[i].x, k2[j].x, acc2[half * 4 + i][j]);
                    acc2[half * 4 + i][j] = fma2(q2[i].y, k2[j].y, acc2[half * 4 + i][j]);
                }
            }
        }
    }

    float acc[8][4];
    #pragma unroll
    for (int i = 0; i < 8; i++)
        #pragma unroll
        for (int j = 0; j < 4; j++) acc[i][j] = fold2(acc2[i][j]);

    // zero the diagonal (only possible within diagonal tile pairs)
    if (ti == tj) {
        #pragma unroll
        for (int i = 0; i < 8; i++)
            #pragma unroll
            for (int j = 0; j < 4; j++)
                if (ty + 16 * i == chunk * TSK + tx + 16 * j) acc[i][j] = 0.0f;
    }

    float* cv = smem;                                     // [128][32]
    int*   ci = reinterpret_cast<int*>(smem) + 128 * 32;

    // ---- Pass 1: row-wise top-2 (q rows of ti vs this 64-col chunk) ----
    __syncthreads();   // done with tiles; reuse smem
    #pragma unroll
    for (int i = 0; i < 8; i++) {
        float v1 = -INFINITY, v2 = -INFINITY;
        int   i1 = 0x7fffffff, i2 = 0x7fffffff;
        #pragma unroll
        for (int j = 0; j < 4; j++)
            top2_update(acc[i][j], kbase + tx + 16 * j, v1, i1, v2, i2);
        int r = ty + 16 * i;
        cv[r * 32 + tx * 2]     = v1; ci[r * 32 + tx * 2]     = i1;
        cv[r * 32 + tx * 2 + 1] = v2; ci[r * 32 + tx * 2 + 1] = i2;
    }
    __syncthreads();
    if (tid < TSQ) {
        float V1 = -INFINITY, V2 = -INFINITY;
        int   I1 = 0x7fffffff, I2 = 0x7fffffff;
        #pragma unroll 8
        for (int c = 0; c < 32; c++)
            top2_update(cv[tid * 32 + c], ci[tid * 32 + c], V1, I1, V2, I2);
        size_t base = ((size_t)(b * MM + ibase + tid) * 32 + (2 * tj + chunk)) * 2;
        g_cand[base]     = make_float2(V1, __int_as_float(I1));
        g_cand[base + 1] = make_float2(V2, __int_as_float(I2));
    }

    // ---- Pass 2: col-wise top-2 (k rows of this chunk vs 128 q cols) ----
    if (ti != tj) {
        __syncthreads();
        #pragma unroll
        for (int j = 0; j < 4; j++) {
            float v1 = -INFINITY, v2 = -INFINITY;
            int   i1 = 0x7fffffff, i2 = 0x7fffffff;
            #pragma unroll
            for (int i = 0; i < 8; i++)
                top2_update(acc[i][j], ibase + ty + 16 * i, v1, i1, v2, i2);
            int c = tx + 16 * j;    // 0..63
            cv[c * 32 + ty * 2]     = v1; ci[c * 32 + ty * 2]     = i1;
            cv[c * 32 + ty * 2 + 1] = v2; ci[c * 32 + ty * 2 + 1] = i2;
        }
        __syncthreads();
        if (tid < TSK) {
            float V1 = -INFINITY, V2 = -INFINITY;
            int   I1 = 0x7fffffff, I2 = 0x7fffffff;
            #pragma unroll 8
            for (int c = 0; c < 32; c++)
                top2_update(cv[tid * 32 + c], ci[tid * 32 + c], V1, I1, V2, I2);
            size_t base = ((size_t)(b * MM + kbase + tid) * 32 + ti) * 2;
            g_cand[base]     = make_float2(V1, __int_as_float(I1));
            g_cand[base + 1] = make_float2(V2, __int_as_float(I2));
        }
    }
}

// ---------------------------------------------------------------------------
// Kernel 3: per-row reduce of candidate slots -> top-2 -> symmetric scatter.
// One warp per row; lane L owns slot L (2 candidates).
// Valid slots for row in tile t: [0, t) from pass-2, [2t, 32) from pass-1.
// ---------------------------------------------------------------------------
__global__ void reduce_kernel(float* __restrict__ out) {
    int row  = blockIdx.x * 8 + (threadIdx.x >> 5);
    int lane = threadIdx.x & 31;
    int m = row & (MM - 1);
    int t = m >> 7;

    float v1 = -INFINITY, v2 = -INFINITY;
    int   i1 = 0x7fffffff, i2 = 0x7fffffff;
    bool valid = (lane < t) || (lane >= 2 * t);
    if (valid) {
        float4 c = reinterpret_cast<const float4*>(g_cand)[(size_t)row * 32 + lane];
        v1 = c.x; i1 = __float_as_int(c.y);
        top2_update(c.z, __float_as_int(c.w), v1, i1, v2, i2);
    }
    #pragma unroll
    for (int o = 16; o > 0; o >>= 1) {
        float ov1 = __shfl_xor_sync(0xffffffffu, v1, o);
        float ov2 = __shfl_xor_sync(0xffffffffu, v2, o);
        int   oi1 = __shfl_xor_sync(0xffffffffu, i1, o);
        int   oi2 = __shfl_xor_sync(0xffffffffu, i2, o);
        top2_merge(ov1, oi1, v1, i1, v2, i2);
        top2_merge(ov2, oi2, v1, i1, v2, i2);
    }
    if (lane == 0) {
        int b = row >> 11;
        float* O = out + (size_t)b * MM * MM;
        atomicAdd(O + (size_t)m * MM + i1, 0.5f * v1);
        atomicAdd(O + (size_t)i1 * MM + m, 0.5f * v1);
        atomicAdd(O + (size_t)m * MM + i2, 0.5f * v2);
        atomicAdd(O + (size_t)i2 * MM + m, 0.5f * v2);
    }
}

// ---------------------------------------------------------------------------
extern "C" void kernel_launch(void* const* d_in, const int* in_sizes, int n_in,
                              void* d_out, int out_size) {
    const float* x = (const float*)d_in[0];
    float* out = (float*)d_out;

    normalize_kernel<<<(BB * MM) / 8, 256>>>(x);

    cudaFuncSetAttribute(pair_kernel,
                         cudaFuncAttributeMaxDynamicSharedMemorySize, SMEM_BYTES);
    dim3 grid(NPAIR, 2, BB);
    pair_kernel<<<grid, 256, SMEM_BYTES>>>(out);

    reduce_kernel<<<(BB * MM) / 8, 256>>>(out);
}